// round 1
// baseline (speedup 1.0000x reference)
#include <cuda_runtime.h>
#include <cstdint>

// Problem constants (fixed shapes for this problem instance)
#define NROI      256
#define NCH       256
#define NPTS      7          // NUM_POINTS
#define HP        8
#define H0F       200
#define W0F       336
#define IMG_W     1344.0f    // W0 / SCALES[0]
#define IMG_H     800.0f     // H0 / SCALES[0]

__device__ int g_lvl[NROI];
__device__ int g_pid[NROI];

// ---------------------------------------------------------------------------
// Per-ROI metadata: FPN level from bbox area (match f32 jnp math exactly),
// pooler id from text length.
// ---------------------------------------------------------------------------
__global__ void prep_kernel(const float* __restrict__ polys,
                            const int* __restrict__ lens, int N) {
    int n = blockIdx.x * blockDim.x + threadIdx.x;
    if (n >= N) return;
    const float* p = polys + (size_t)n * (2 * NPTS * 2);
    float minx = p[0], maxx = p[0], miny = p[1], maxy = p[1];
#pragma unroll
    for (int i = 1; i < 2 * NPTS; i++) {
        float x = p[2 * i], y = p[2 * i + 1];
        minx = fminf(minx, x); maxx = fmaxf(maxx, x);
        miny = fminf(miny, y); maxy = fmaxf(maxy, y);
    }
    float s = sqrtf((maxx - minx) * (maxy - miny));
    float v = 4.0f + log2f(s / 224.0f + 1e-6f);   // CANON_LVL + log2(s/CANON_SCALE + eps)
    float fl = floorf(v);
    fl = fminf(fmaxf(fl, 2.0f), 5.0f);            // clip(K_MIN, K_MAX)
    g_lvl[n] = (int)fl - 2;                       // - K_MIN
    g_pid[n] = (lens[n] > 8) ? 1 : 0;             // thr = LENS_AREA[0] = 8
}

// ---------------------------------------------------------------------------
// Main pooling kernel. One launch per output tensor (WP=32 -> pid 0,
// WP=64 -> pid 1). Grid: (NCH*HP*WP/256, NROI). Each thread = one output
// element (n, c, y, x); x fastest -> coalesced stores, near-coalesced gathers.
// ---------------------------------------------------------------------------
template <int WP, int PID>
__global__ void __launch_bounds__(256)
pool_kernel(const float* __restrict__ f0, const float* __restrict__ f1,
            const float* __restrict__ f2, const float* __restrict__ f3,
            const float* __restrict__ polys, const int* __restrict__ img_ids,
            float* __restrict__ out) {
    const int n = blockIdx.y;

    __shared__ float sp[2 * NPTS * 2];   // 28 floats: this ROI's polygon
    __shared__ int s_meta[3];            // lvl, pid, img_id
    if (threadIdx.x < 2 * NPTS * 2)
        sp[threadIdx.x] = polys[(size_t)n * (2 * NPTS * 2) + threadIdx.x];
    if (threadIdx.x == 0) {
        s_meta[0] = g_lvl[n];
        s_meta[1] = g_pid[n];
        s_meta[2] = img_ids[n];
    }
    __syncthreads();

    const int e = blockIdx.x * blockDim.x + threadIdx.x;   // index within this ROI
    const int x = e % WP;
    const int y = (e / WP) % HP;
    const int c = e / (WP * HP);

    float* o = out + (((size_t)n * NCH + c) * HP + y) * WP + x;

    if (s_meta[1] != PID) {   // ROI belongs to the other pooler: dense zeros
        *o = 0.0f;
        return;
    }

    // --- sampling grid (matches _make_grid) ---
    // top boundary = poly points 0..6 ; bottom boundary = points 13..7 (reversed)
    float u = (x + 0.5f) * ((float)(NPTS - 1) / (float)WP);
    int i0 = (int)floorf(u);
    i0 = max(0, min(i0, NPTS - 2));
    float f = u - (float)i0;
    const float invW = 1.0f / IMG_W, invH = 1.0f / IMG_H;

    float tx = (sp[2 * i0]     * (1.0f - f) + sp[2 * (i0 + 1)]     * f) * invW;
    float ty = (sp[2 * i0 + 1] * (1.0f - f) + sp[2 * (i0 + 1) + 1] * f) * invH;
    int j0 = 13 - i0, j1 = 12 - i0;
    float bx = (sp[2 * j0]     * (1.0f - f) + sp[2 * j1]     * f) * invW;
    float by = (sp[2 * j0 + 1] * (1.0f - f) + sp[2 * j1 + 1] * f) * invH;

    float v  = (y + 0.5f) * (1.0f / HP);
    float gx = tx * (1.0f - v) + bx * v;
    float gy = ty * (1.0f - v) + by * v;

    // --- select feature level ---
    int lvl = s_meta[0];
    int H, W;
    const float* feat;
    switch (lvl) {
        case 0:  H = H0F;     W = W0F;     feat = f0; break;
        case 1:  H = H0F / 2; W = W0F / 2; feat = f1; break;
        case 2:  H = H0F / 4; W = W0F / 4; feat = f2; break;
        default: H = H0F / 8; W = W0F / 8; feat = f3; break;
    }

    // --- bilinear sample (align_corners=False convention, zero-mask OOB) ---
    float xf = gx * (float)W - 0.5f;
    float yf = gy * (float)H - 0.5f;
    float x0f = floorf(xf), y0f = floorf(yf);
    float wx = xf - x0f, wy = yf - y0f;
    int x0 = (int)x0f, y0 = (int)y0f;
    int x1 = x0 + 1,   y1 = y0 + 1;

    const float* base = feat + (size_t)(s_meta[2] * NCH + c) * (size_t)H * (size_t)W;

    int x0c = min(max(x0, 0), W - 1), x1c = min(max(x1, 0), W - 1);
    int y0c = min(max(y0, 0), H - 1), y1c = min(max(y1, 0), H - 1);
    float m00 = (x0 >= 0 && x0 < W && y0 >= 0 && y0 < H) ? 1.0f : 0.0f;
    float m10 = (x1 >= 0 && x1 < W && y0 >= 0 && y0 < H) ? 1.0f : 0.0f;
    float m01 = (x0 >= 0 && x0 < W && y1 >= 0 && y1 < H) ? 1.0f : 0.0f;
    float m11 = (x1 >= 0 && x1 < W && y1 >= 0 && y1 < H) ? 1.0f : 0.0f;

    float v00 = __ldg(base + (size_t)y0c * W + x0c) * m00;
    float v10 = __ldg(base + (size_t)y0c * W + x1c) * m10;
    float v01 = __ldg(base + (size_t)y1c * W + x0c) * m01;
    float v11 = __ldg(base + (size_t)y1c * W + x1c) * m11;

    float r = v00 * (1.0f - wx) * (1.0f - wy)
            + v10 * wx          * (1.0f - wy)
            + v01 * (1.0f - wx) * wy
            + v11 * wx          * wy;
    *o = r;
}

extern "C" void kernel_launch(void* const* d_in, const int* in_sizes, int n_in,
                              void* d_out, int out_size) {
    const float* f0     = (const float*)d_in[0];
    const float* f1     = (const float*)d_in[1];
    const float* f2     = (const float*)d_in[2];
    const float* f3     = (const float*)d_in[3];
    const float* polys  = (const float*)d_in[4];
    const int*   imgids = (const int*)  d_in[5];
    const int*   lens   = (const int*)  d_in[6];
    float* out = (float*)d_out;

    const int N = in_sizes[4] / (2 * NPTS * 2);   // 256

    prep_kernel<<<(N + 255) / 256, 256>>>(polys, lens, N);

    // Output 0: (N, C, 8, 32), pooler id 0
    {
        dim3 grid(NCH * HP * 32 / 256, N);
        pool_kernel<32, 0><<<grid, 256>>>(f0, f1, f2, f3, polys, imgids, out);
    }
    // Output 1: (N, C, 8, 64), pooler id 1
    {
        float* out1 = out + (size_t)N * NCH * HP * 32;
        dim3 grid(NCH * HP * 64 / 256, N);
        pool_kernel<64, 1><<<grid, 256>>>(f0, f1, f2, f3, polys, imgids, out1);
    }
}

// round 2
// speedup vs baseline: 1.0689x; 1.0689x over previous
#include <cuda_runtime.h>
#include <cstdint>

// Problem constants (fixed shapes for this problem instance)
#define NROI      256
#define NCH       256
#define NPTS      7          // NUM_POINTS
#define HP        8
#define H0F       200
#define W0F       336
#define IMG_W     1344.0f    // W0 / SCALES[0]
#define IMG_H     800.0f     // H0 / SCALES[0]

// ---------------------------------------------------------------------------
// Fused pooler. One launch per output tensor (WP=32 -> pid 0, WP=64 -> pid 1).
// Each thread computes 4 consecutive x outputs -> one float4 store.
// Per-ROI metadata (bbox level, pooler id) computed per block in thread 0
// from the smem-staged polygon (cheap: 14 points).
//
// Thread layout per block (256 threads):
//   WP=32: QUADS=8,  64 threads/channel, 4 channels/block, gridDim.x = 64
//   WP=64: QUADS=16, 128 threads/channel, 2 channels/block, gridDim.x = 128
// gridDim.y = NROI.
// ---------------------------------------------------------------------------
template <int WP, int PID>
__global__ void __launch_bounds__(256)
pool_kernel(const float* __restrict__ f0, const float* __restrict__ f1,
            const float* __restrict__ f2, const float* __restrict__ f3,
            const float* __restrict__ polys, const int* __restrict__ img_ids,
            const int* __restrict__ lens, float* __restrict__ out) {
    const int n = blockIdx.y;

    constexpr int QUADS = WP / 4;
    constexpr int TPC   = QUADS * HP;     // threads per channel
    constexpr int CPB   = 256 / TPC;      // channels per block

    __shared__ float sp[2 * NPTS * 2];    // 28 floats: this ROI's polygon
    __shared__ int s_lvl, s_pid, s_img;

    if (threadIdx.x < 2 * NPTS * 2)
        sp[threadIdx.x] = polys[(size_t)n * (2 * NPTS * 2) + threadIdx.x];
    __syncthreads();

    if (threadIdx.x == 0) {
        float minx = sp[0], maxx = sp[0], miny = sp[1], maxy = sp[1];
#pragma unroll
        for (int i = 1; i < 2 * NPTS; i++) {
            float px = sp[2 * i], py = sp[2 * i + 1];
            minx = fminf(minx, px); maxx = fmaxf(maxx, px);
            miny = fminf(miny, py); maxy = fmaxf(maxy, py);
        }
        float s  = sqrtf((maxx - minx) * (maxy - miny));
        float vv = 4.0f + log2f(s / 224.0f + 1e-6f);   // CANON_LVL + log2(s/CANON + eps)
        float fl = fminf(fmaxf(floorf(vv), 2.0f), 5.0f);
        s_lvl = (int)fl - 2;
        s_pid = (lens[n] > 8) ? 1 : 0;
        s_img = img_ids[n];
    }
    __syncthreads();

    const int quad = threadIdx.x % QUADS;
    const int y    = (threadIdx.x / QUADS) % HP;
    const int cl   = threadIdx.x / TPC;
    const int c    = blockIdx.x * CPB + cl;

    float4* o = (float4*)(out + (((size_t)n * NCH + c) * HP + y) * WP + quad * 4);

    if (s_pid != PID) {                    // ROI belongs to the other pooler
        *o = make_float4(0.f, 0.f, 0.f, 0.f);
        return;
    }

    // --- select feature level ---
    int H, W;
    const float* feat;
    switch (s_lvl) {
        case 0:  H = H0F;     W = W0F;     feat = f0; break;
        case 1:  H = H0F / 2; W = W0F / 2; feat = f1; break;
        case 2:  H = H0F / 4; W = W0F / 4; feat = f2; break;
        default: H = H0F / 8; W = W0F / 8; feat = f3; break;
    }
    const float* base = feat + (size_t)(s_img * NCH + c) * (size_t)H * (size_t)W;

    const float v    = (y + 0.5f) * (1.0f / HP);
    const float invW = 1.0f / IMG_W, invH = 1.0f / IMG_H;

    // Per-sample texel coords / weights, then batched gathers for MLP.
    int   off00[4], off10[4], off01[4], off11[4];
    float mk00[4], mk10[4], mk01[4], mk11[4];
    float wxk[4], wyk[4];

#pragma unroll
    for (int k = 0; k < 4; k++) {
        const int x = quad * 4 + k;
        // boundary interp: top = pts 0..6, bottom = pts 13..7 (reversed)
        float u = (x + 0.5f) * ((float)(NPTS - 1) / (float)WP);
        int i0 = (int)floorf(u);
        i0 = max(0, min(i0, NPTS - 2));
        float f = u - (float)i0;
        int j0 = 13 - i0, j1 = 12 - i0;

        float tx = (sp[2 * i0]     * (1.0f - f) + sp[2 * (i0 + 1)]     * f) * invW;
        float ty = (sp[2 * i0 + 1] * (1.0f - f) + sp[2 * (i0 + 1) + 1] * f) * invH;
        float bx = (sp[2 * j0]     * (1.0f - f) + sp[2 * j1]     * f) * invW;
        float by = (sp[2 * j0 + 1] * (1.0f - f) + sp[2 * j1 + 1] * f) * invH;

        float gx = tx * (1.0f - v) + bx * v;
        float gy = ty * (1.0f - v) + by * v;

        float xf = gx * (float)W - 0.5f;
        float yf = gy * (float)H - 0.5f;
        float x0f = floorf(xf), y0f = floorf(yf);
        wxk[k] = xf - x0f;
        wyk[k] = yf - y0f;
        int x0 = (int)x0f, y0 = (int)y0f;
        int x1 = x0 + 1,   y1 = y0 + 1;

        int x0c = min(max(x0, 0), W - 1), x1c = min(max(x1, 0), W - 1);
        int y0c = min(max(y0, 0), H - 1), y1c = min(max(y1, 0), H - 1);
        bool xin0 = (x0 >= 0) & (x0 < W), xin1 = (x1 >= 0) & (x1 < W);
        bool yin0 = (y0 >= 0) & (y0 < H), yin1 = (y1 >= 0) & (y1 < H);
        mk00[k] = (xin0 & yin0) ? 1.0f : 0.0f;
        mk10[k] = (xin1 & yin0) ? 1.0f : 0.0f;
        mk01[k] = (xin0 & yin1) ? 1.0f : 0.0f;
        mk11[k] = (xin1 & yin1) ? 1.0f : 0.0f;
        off00[k] = y0c * W + x0c;
        off10[k] = y0c * W + x1c;
        off01[k] = y1c * W + x0c;
        off11[k] = y1c * W + x1c;
    }

    // batched gathers (16 independent LDGs in flight)
    float v00[4], v10[4], v01[4], v11[4];
#pragma unroll
    for (int k = 0; k < 4; k++) v00[k] = __ldg(base + off00[k]);
#pragma unroll
    for (int k = 0; k < 4; k++) v10[k] = __ldg(base + off10[k]);
#pragma unroll
    for (int k = 0; k < 4; k++) v01[k] = __ldg(base + off01[k]);
#pragma unroll
    for (int k = 0; k < 4; k++) v11[k] = __ldg(base + off11[k]);

    float r[4];
#pragma unroll
    for (int k = 0; k < 4; k++) {
        float wx = wxk[k], wy = wyk[k];
        r[k] = v00[k] * mk00[k] * (1.0f - wx) * (1.0f - wy)
             + v10[k] * mk10[k] * wx          * (1.0f - wy)
             + v01[k] * mk01[k] * (1.0f - wx) * wy
             + v11[k] * mk11[k] * wx          * wy;
    }
    *o = make_float4(r[0], r[1], r[2], r[3]);
}

extern "C" void kernel_launch(void* const* d_in, const int* in_sizes, int n_in,
                              void* d_out, int out_size) {
    const float* f0     = (const float*)d_in[0];
    const float* f1     = (const float*)d_in[1];
    const float* f2     = (const float*)d_in[2];
    const float* f3     = (const float*)d_in[3];
    const float* polys  = (const float*)d_in[4];
    const int*   imgids = (const int*)  d_in[5];
    const int*   lens   = (const int*)  d_in[6];
    float* out = (float*)d_out;

    const int N = in_sizes[4] / (2 * NPTS * 2);   // 256

    // Output 0: (N, C, 8, 32), pooler id 0
    {
        dim3 grid(NCH / 4, N);       // 4 channels per block
        pool_kernel<32, 0><<<grid, 256>>>(f0, f1, f2, f3, polys, imgids, lens, out);
    }
    // Output 1: (N, C, 8, 64), pooler id 1
    {
        float* out1 = out + (size_t)N * NCH * HP * 32;
        dim3 grid(NCH / 2, N);       // 2 channels per block
        pool_kernel<64, 1><<<grid, 256>>>(f0, f1, f2, f3, polys, imgids, lens, out1);
    }
}

// round 3
// speedup vs baseline: 1.3239x; 1.2386x over previous
#include <cuda_runtime.h>
#include <cstdint>

#define NROI      256
#define NCH       256
#define NPTS      7
#define HP        8
#define H0F       200
#define W0F       336
#define IMG_W     1344.0f
#define IMG_H     800.0f

// ---------------------------------------------------------------------------
// Grid-hoisted pooler. The sampling grid depends only on (roi, y, x) -> each
// thread owns one (y, 4-wide x quad) position, computes 16 gather offsets and
// 16 mask-fused bilinear weights ONCE, then streams its channel slice:
// per channel = 16 LDG + 16 FMA + 1 STG.128.
//
// Block: 256 threads = NPOS position-threads x NSUB channel-subsets.
// Grid:  (NCH / CCHUNK, NROI). Each thread loops CCHUNK/NSUB channels.
// ---------------------------------------------------------------------------
template <int WP, int PID, int CCHUNK>
__global__ void __launch_bounds__(256)
pool_kernel(const float* __restrict__ f0, const float* __restrict__ f1,
            const float* __restrict__ f2, const float* __restrict__ f3,
            const float* __restrict__ polys, const int* __restrict__ img_ids,
            const int* __restrict__ lens, float* __restrict__ out) {
    const int n = blockIdx.y;

    constexpr int QUADS = WP / 4;
    constexpr int NPOS  = HP * QUADS;      // 128 (WP=64) or 64 (WP=32)
    constexpr int NSUB  = 256 / NPOS;      // 2 or 4
    constexpr int CPT   = CCHUNK / NSUB;   // channels per thread: 16 or 8

    __shared__ float sp[2 * NPTS * 2];
    __shared__ int s_lvl, s_pid, s_img;

    if (threadIdx.x < 2 * NPTS * 2)
        sp[threadIdx.x] = polys[(size_t)n * (2 * NPTS * 2) + threadIdx.x];
    __syncthreads();

    if (threadIdx.x == 0) {
        float minx = sp[0], maxx = sp[0], miny = sp[1], maxy = sp[1];
#pragma unroll
        for (int i = 1; i < 2 * NPTS; i++) {
            float px = sp[2 * i], py = sp[2 * i + 1];
            minx = fminf(minx, px); maxx = fmaxf(maxx, px);
            miny = fminf(miny, py); maxy = fmaxf(maxy, py);
        }
        float s  = sqrtf((maxx - minx) * (maxy - miny));
        float vv = 4.0f + log2f(s / 224.0f + 1e-6f);
        float fl = fminf(fmaxf(floorf(vv), 2.0f), 5.0f);
        s_lvl = (int)fl - 2;
        s_pid = (lens[n] > 8) ? 1 : 0;
        s_img = img_ids[n];
    }
    __syncthreads();

    const int pos  = threadIdx.x % NPOS;
    const int sub  = threadIdx.x / NPOS;
    const int quad = pos % QUADS;
    const int y    = pos / QUADS;
    const int c0   = blockIdx.x * CCHUNK + sub;   // channel stride NSUB

    float* op = out + (((size_t)n * NCH + c0) * HP + y) * WP + quad * 4;
    constexpr size_t OSTRIDE = (size_t)NSUB * HP * WP;

    if (s_pid != PID) {                    // other pooler: dense zeros
        const float4 z = make_float4(0.f, 0.f, 0.f, 0.f);
#pragma unroll
        for (int i = 0; i < CPT; i++) {
            *(float4*)op = z;
            op += OSTRIDE;
        }
        return;
    }

    int H, W;
    const float* feat;
    switch (s_lvl) {
        case 0:  H = H0F;     W = W0F;     feat = f0; break;
        case 1:  H = H0F / 2; W = W0F / 2; feat = f1; break;
        case 2:  H = H0F / 4; W = W0F / 4; feat = f2; break;
        default: H = H0F / 8; W = W0F / 8; feat = f3; break;
    }
    const size_t HW = (size_t)H * W;
    const float* p = feat + ((size_t)s_img * NCH + c0) * HW;

    const float v    = (y + 0.5f) * (1.0f / HP);
    const float invW = 1.0f / IMG_W, invH = 1.0f / IMG_H;

    // --- per-position precompute: 16 offsets + 16 mask-fused weights ---
    int   off00[4], off10[4], off01[4], off11[4];
    float w00[4], w10[4], w01[4], w11[4];

#pragma unroll
    for (int k = 0; k < 4; k++) {
        const int x = quad * 4 + k;
        float u = (x + 0.5f) * ((float)(NPTS - 1) / (float)WP);
        int i0 = (int)floorf(u);
        i0 = max(0, min(i0, NPTS - 2));
        float f = u - (float)i0;
        int j0 = 13 - i0, j1 = 12 - i0;

        float tx = (sp[2 * i0]     * (1.0f - f) + sp[2 * (i0 + 1)]     * f) * invW;
        float ty = (sp[2 * i0 + 1] * (1.0f - f) + sp[2 * (i0 + 1) + 1] * f) * invH;
        float bx = (sp[2 * j0]     * (1.0f - f) + sp[2 * j1]     * f) * invW;
        float by = (sp[2 * j0 + 1] * (1.0f - f) + sp[2 * j1 + 1] * f) * invH;

        float gx = tx * (1.0f - v) + bx * v;
        float gy = ty * (1.0f - v) + by * v;

        float xf = gx * (float)W - 0.5f;
        float yf = gy * (float)H - 0.5f;
        float x0f = floorf(xf), y0f = floorf(yf);
        float wx = xf - x0f, wy = yf - y0f;
        int x0 = (int)x0f, y0 = (int)y0f;
        int x1 = x0 + 1,   y1 = y0 + 1;

        int x0c = min(max(x0, 0), W - 1), x1c = min(max(x1, 0), W - 1);
        int y0c = min(max(y0, 0), H - 1), y1c = min(max(y1, 0), H - 1);
        float m00 = ((x0 >= 0) & (x0 < W) & (y0 >= 0) & (y0 < H)) ? 1.0f : 0.0f;
        float m10 = ((x1 >= 0) & (x1 < W) & (y0 >= 0) & (y0 < H)) ? 1.0f : 0.0f;
        float m01 = ((x0 >= 0) & (x0 < W) & (y1 >= 0) & (y1 < H)) ? 1.0f : 0.0f;
        float m11 = ((x1 >= 0) & (x1 < W) & (y1 >= 0) & (y1 < H)) ? 1.0f : 0.0f;

        w00[k] = m00 * (1.0f - wx) * (1.0f - wy);
        w10[k] = m10 * wx          * (1.0f - wy);
        w01[k] = m01 * (1.0f - wx) * wy;
        w11[k] = m11 * wx          * wy;

        off00[k] = y0c * W + x0c;
        off10[k] = y0c * W + x1c;
        off01[k] = y1c * W + x0c;
        off11[k] = y1c * W + x1c;
    }

    // --- channel stream: 16 LDG + 16 FMA + 1 STG.128 per channel ---
#pragma unroll 2
    for (int i = 0; i < CPT; i++) {
        float v00[4], v10[4], v01[4], v11[4];
#pragma unroll
        for (int k = 0; k < 4; k++) v00[k] = __ldg(p + off00[k]);
#pragma unroll
        for (int k = 0; k < 4; k++) v10[k] = __ldg(p + off10[k]);
#pragma unroll
        for (int k = 0; k < 4; k++) v01[k] = __ldg(p + off01[k]);
#pragma unroll
        for (int k = 0; k < 4; k++) v11[k] = __ldg(p + off11[k]);

        float r[4];
#pragma unroll
        for (int k = 0; k < 4; k++) {
            r[k] = v00[k] * w00[k] + v10[k] * w10[k]
                 + v01[k] * w01[k] + v11[k] * w11[k];
        }
        *(float4*)op = make_float4(r[0], r[1], r[2], r[3]);
        p  += (size_t)NSUB * HW;
        op += OSTRIDE;
    }
}

extern "C" void kernel_launch(void* const* d_in, const int* in_sizes, int n_in,
                              void* d_out, int out_size) {
    const float* f0     = (const float*)d_in[0];
    const float* f1     = (const float*)d_in[1];
    const float* f2     = (const float*)d_in[2];
    const float* f3     = (const float*)d_in[3];
    const float* polys  = (const float*)d_in[4];
    const int*   imgids = (const int*)  d_in[5];
    const int*   lens   = (const int*)  d_in[6];
    float* out = (float*)d_out;

    const int N = in_sizes[4] / (2 * NPTS * 2);   // 256

    // Output 0: (N, C, 8, 32), pooler id 0
    {
        dim3 grid(NCH / 32, N);
        pool_kernel<32, 0, 32><<<grid, 256>>>(f0, f1, f2, f3, polys, imgids, lens, out);
    }
    // Output 1: (N, C, 8, 64), pooler id 1
    {
        float* out1 = out + (size_t)N * NCH * HP * 32;
        dim3 grid(NCH / 32, N);
        pool_kernel<64, 1, 32><<<grid, 256>>>(f0, f1, f2, f3, polys, imgids, lens, out1);
    }
}

// round 4
// speedup vs baseline: 1.8512x; 1.3983x over previous
#include <cuda_runtime.h>
#include <cstdint>

#define NROI      256
#define NCH       256
#define NPTS      7
#define HP        8
#define H0F       200
#define W0F       336
#define IMG_W     1344.0f
#define IMG_H     800.0f
#define CCHUNK    16          // channels per block

// ---------------------------------------------------------------------------
// Fused dual-output pooler, one launch.
//  grid = (32, NROI): blockIdx.x < 16 -> output0 (WP=32, pid0) chunk,
//                     blockIdx.x >= 16 -> output1 (WP=64, pid1) chunk.
// Sampling grid depends only on (roi, y, x): per position, 16 gather offsets
// go to smem (shared across channel-subset replicas), 16 mask-fused weights
// stay in registers. Inner loop per channel: 16 LDG + 16 FMA + 1 STG.128.
// Blocks whose ROI belongs to the other pooler stream float4 zeros.
// ---------------------------------------------------------------------------

template <int WP, int PID>
__device__ __forceinline__ void pool_body(
    int cx, int n,
    const float* __restrict__ f0, const float* __restrict__ f1,
    const float* __restrict__ f2, const float* __restrict__ f3,
    float* __restrict__ outp,
    const float* sp, int s_lvl, int s_pid, int s_img,
    int* s_off) {

    constexpr int QUADS = WP / 4;
    constexpr int NPOS  = HP * QUADS;      // 64 (WP=32) / 128 (WP=64)
    constexpr int NSUB  = 256 / NPOS;      // 4 / 2
    constexpr int CPT   = CCHUNK / NSUB;   // 4 / 8

    const int pos  = threadIdx.x % NPOS;
    const int sub  = threadIdx.x / NPOS;
    const int quad = pos % QUADS;
    const int y    = pos / QUADS;
    const int c0   = cx * CCHUNK + sub;

    float* op = outp + (((size_t)n * NCH + c0) * HP + y) * WP + quad * 4;
    constexpr size_t OST = (size_t)NSUB * HP * WP;

    if (s_pid != PID) {                    // other pooler: dense zeros
        const float4 z = make_float4(0.f, 0.f, 0.f, 0.f);
#pragma unroll
        for (int i = 0; i < CPT; i++) { *(float4*)op = z; op += OST; }
        return;
    }

    int H, W;
    const float* feat;
    switch (s_lvl) {
        case 0:  H = H0F;     W = W0F;     feat = f0; break;
        case 1:  H = H0F / 2; W = W0F / 2; feat = f1; break;
        case 2:  H = H0F / 4; W = W0F / 4; feat = f2; break;
        default: H = H0F / 8; W = W0F / 8; feat = f3; break;
    }
    const size_t HW = (size_t)H * W;
    const float* p = feat + ((size_t)s_img * NCH + c0) * HW;

    const float v    = (y + 0.5f) * (1.0f / HP);
    const float invW = 1.0f / IMG_W, invH = 1.0f / IMG_H;

    float w00[4], w10[4], w01[4], w11[4];

#pragma unroll
    for (int k = 0; k < 4; k++) {
        const int x = quad * 4 + k;
        float u = (x + 0.5f) * ((float)(NPTS - 1) / (float)WP);
        int i0 = (int)floorf(u);
        i0 = max(0, min(i0, NPTS - 2));
        float f = u - (float)i0;
        int j0 = 13 - i0, j1 = 12 - i0;

        float tx = (sp[2 * i0]     * (1.0f - f) + sp[2 * (i0 + 1)]     * f) * invW;
        float ty = (sp[2 * i0 + 1] * (1.0f - f) + sp[2 * (i0 + 1) + 1] * f) * invH;
        float bx = (sp[2 * j0]     * (1.0f - f) + sp[2 * j1]     * f) * invW;
        float by = (sp[2 * j0 + 1] * (1.0f - f) + sp[2 * j1 + 1] * f) * invH;

        float gx = tx * (1.0f - v) + bx * v;
        float gy = ty * (1.0f - v) + by * v;

        float xf = gx * (float)W - 0.5f;
        float yf = gy * (float)H - 0.5f;
        float x0f = floorf(xf), y0f = floorf(yf);
        float wx = xf - x0f, wy = yf - y0f;
        int x0 = (int)x0f, y0i = (int)y0f;
        int x1 = x0 + 1,   y1 = y0i + 1;

        int x0c = min(max(x0, 0), W - 1), x1c = min(max(x1, 0), W - 1);
        int y0c = min(max(y0i, 0), H - 1), y1c = min(max(y1, 0), H - 1);
        float m00 = ((x0 >= 0) & (x0 < W) & (y0i >= 0) & (y0i < H)) ? 1.0f : 0.0f;
        float m10 = ((x1 >= 0) & (x1 < W) & (y0i >= 0) & (y0i < H)) ? 1.0f : 0.0f;
        float m01 = ((x0 >= 0) & (x0 < W) & (y1 >= 0) & (y1 < H)) ? 1.0f : 0.0f;
        float m11 = ((x1 >= 0) & (x1 < W) & (y1 >= 0) & (y1 < H)) ? 1.0f : 0.0f;

        w00[k] = m00 * (1.0f - wx) * (1.0f - wy);
        w10[k] = m10 * wx          * (1.0f - wy);
        w01[k] = m01 * (1.0f - wx) * wy;
        w11[k] = m11 * wx          * wy;

        if (sub == 0) {
            s_off[pos * 16 + k * 4 + 0] = y0c * W + x0c;
            s_off[pos * 16 + k * 4 + 1] = y0c * W + x1c;
            s_off[pos * 16 + k * 4 + 2] = y1c * W + x0c;
            s_off[pos * 16 + k * 4 + 3] = y1c * W + x1c;
        }
    }
    __syncthreads();

    const int* __restrict__ so = s_off + pos * 16;

#pragma unroll 2
    for (int i = 0; i < CPT; i++) {
        float vv[16];
#pragma unroll
        for (int t = 0; t < 16; t++) vv[t] = __ldg(p + so[t]);
        float r[4];
#pragma unroll
        for (int k = 0; k < 4; k++) {
            r[k] = vv[k*4+0] * w00[k] + vv[k*4+1] * w10[k]
                 + vv[k*4+2] * w01[k] + vv[k*4+3] * w11[k];
        }
        *(float4*)op = make_float4(r[0], r[1], r[2], r[3]);
        p  += (size_t)NSUB * HW;
        op += OST;
    }
}

__global__ void __launch_bounds__(256, 3)
fused_pool_kernel(const float* __restrict__ f0, const float* __restrict__ f1,
                  const float* __restrict__ f2, const float* __restrict__ f3,
                  const float* __restrict__ polys, const int* __restrict__ img_ids,
                  const int* __restrict__ lens, float* __restrict__ out) {
    const int n = blockIdx.y;

    __shared__ float sp[2 * NPTS * 2];
    __shared__ int s_lvl, s_pid, s_img;
    __shared__ int s_off[128 * 16];        // max NPOS * 16 offsets

    if (threadIdx.x < 2 * NPTS * 2)
        sp[threadIdx.x] = polys[(size_t)n * (2 * NPTS * 2) + threadIdx.x];
    __syncthreads();

    if (threadIdx.x == 0) {
        float minx = sp[0], maxx = sp[0], miny = sp[1], maxy = sp[1];
#pragma unroll
        for (int i = 1; i < 2 * NPTS; i++) {
            float px = sp[2 * i], py = sp[2 * i + 1];
            minx = fminf(minx, px); maxx = fmaxf(maxx, px);
            miny = fminf(miny, py); maxy = fmaxf(maxy, py);
        }
        float s  = sqrtf((maxx - minx) * (maxy - miny));
        float vv = 4.0f + log2f(s / 224.0f + 1e-6f);
        float fl = fminf(fmaxf(floorf(vv), 2.0f), 5.0f);
        s_lvl = (int)fl - 2;
        s_pid = (lens[n] > 8) ? 1 : 0;
        s_img = img_ids[n];
    }
    __syncthreads();

    constexpr int CHUNKS = NCH / CCHUNK;   // 16 per output

    if (blockIdx.x < CHUNKS) {
        // Output 0: (N, C, 8, 32), pooler 0
        pool_body<32, 0>(blockIdx.x, n, f0, f1, f2, f3,
                         out, sp, s_lvl, s_pid, s_img, s_off);
    } else {
        // Output 1: (N, C, 8, 64), pooler 1
        float* out1 = out + (size_t)NROI * NCH * HP * 32;
        pool_body<64, 1>(blockIdx.x - CHUNKS, n, f0, f1, f2, f3,
                         out1, sp, s_lvl, s_pid, s_img, s_off);
    }
}

extern "C" void kernel_launch(void* const* d_in, const int* in_sizes, int n_in,
                              void* d_out, int out_size) {
    const float* f0     = (const float*)d_in[0];
    const float* f1     = (const float*)d_in[1];
    const float* f2     = (const float*)d_in[2];
    const float* f3     = (const float*)d_in[3];
    const float* polys  = (const float*)d_in[4];
    const int*   imgids = (const int*)  d_in[5];
    const int*   lens   = (const int*)  d_in[6];
    float* out = (float*)d_out;

    const int N = in_sizes[4] / (2 * NPTS * 2);   // 256

    dim3 grid(2 * (NCH / CCHUNK), N);             // 32 x 256
    fused_pool_kernel<<<grid, 256>>>(f0, f1, f2, f3, polys, imgids, lens, out);
}